// round 4
// baseline (speedup 1.0000x reference)
#include <cuda_runtime.h>

#define L   8192
#define F   9
#define NT  1024
#define CH  8                 // rows per thread (L / NT)
#define PL  (L + (L >> 3))    // padded length: 9216 floats

// Padded smem index: stride between adjacent threads' rows becomes 9 floats
// -> gcd(9,32)=1 -> conflict-free for the chunked access pattern.
__device__ __forceinline__ int pidx(int t) { return t + (t >> 3); }

__device__ __forceinline__ float adjv(float v) {
    return (v > 1e-13f) ? v : (v + 1.0f);
}
__device__ __forceinline__ float clip01(float x) {
    return fminf(fmaxf(x, 0.0f), 0.9999f);
}

__global__ __launch_bounds__(NT, 1)
void kenneth_kernel(const float* __restrict__ conc,
                    const float* __restrict__ kern,
                    float* __restrict__ out) {
    extern __shared__ float sm[];
    float* sp = sm;            // P[t] (padded)
    float* qf = sm + PL;       // Q_f  (padded)
    float* qb = sm + 2 * PL;   // Q_b  (padded)
    __shared__ float wredp[32], wredf[32], wredb[32];

    const int tid  = threadIdx.x;
    const int lane = tid & 31;
    const int wid  = tid >> 5;
    const float k  = kern[0];
    const float* gin = conc + (size_t)blockIdx.x * L * F;

    // ---- Phase 1: vectorized load of own 8 rows; rowsums + bcd in registers ----
    float rs[CH];
    float bcd[CH];
#pragma unroll
    for (int r = 0; r < CH; r++) rs[r] = 0.0f;
    {
        const float4* g4 = reinterpret_cast<const float4*>(gin) + tid * 18;
#pragma unroll
        for (int v = 0; v < 18; v++) {
            float4 q = g4[v];
#pragma unroll
            for (int e = 0; e < 4; e++) {
                float val = (e == 0) ? q.x : (e == 1) ? q.y : (e == 2) ? q.z : q.w;
                int p = 4 * v + e;
                int r = p / 9;
                int c = p - 9 * r;
                rs[r] += val;
                if (c == 0) bcd[r] = val;
            }
        }
    }

    // ---- Phase 2: block scan of rowsums (register-direct), P = 1 + cumsum ----
    {
        // local inclusive prefix
#pragma unroll
        for (int j = 1; j < CH; j++) rs[j] += rs[j - 1];
        float tot = rs[CH - 1];
        float x = tot;
#pragma unroll
        for (int d = 1; d < 32; d <<= 1) {
            float y = __shfl_up_sync(0xFFFFFFFFu, x, d);
            if (lane >= d) x += y;
        }
        if (lane == 31) wredp[wid] = x;
        __syncthreads();
        if (wid == 0) {
            float w = wredp[lane];
#pragma unroll
            for (int d = 1; d < 32; d <<= 1) {
                float y = __shfl_up_sync(0xFFFFFFFFu, w, d);
                if (lane >= d) w += y;
            }
            wredp[lane] = w;
        }
        __syncthreads();
        float off = 1.0f + (x - tot) + (wid > 0 ? wredp[wid - 1] : 0.0f);
#pragma unroll
        for (int j = 0; j < CH; j++) sp[pidx(CH * tid + j)] = off + rs[j];
    }
    __syncthreads();

    const float Z1 = sp[pidx(L - 1)];
    const float C2 = Z1 + 1.0f;

    // ---- Phase 3+4: build q_f, q_b in registers; fused dual block scan ----
    float qfv[CH], qbv[CH];
#pragma unroll
    for (int j = 0; j < CH; j++) {
        int i = CH * tid + j;
        float pf = (i >= 14) ? sp[pidx(i - 14)] : 1.0f;
        float sv = (i + 14 < L) ? (C2 - sp[pidx(i + 13)]) : 1.0f;
        qfv[j] = bcd[j] * pf;
        qbv[j] = bcd[j] * sv;
    }
#pragma unroll
    for (int j = 1; j < CH; j++) { qfv[j] += qfv[j - 1]; qbv[j] += qbv[j - 1]; }
    float tf = qfv[CH - 1], tb = qbv[CH - 1];
    float xf = tf, xb = tb;
#pragma unroll
    for (int d = 1; d < 32; d <<= 1) {
        float yf = __shfl_up_sync(0xFFFFFFFFu, xf, d);
        float yb = __shfl_up_sync(0xFFFFFFFFu, xb, d);
        if (lane >= d) { xf += yf; xb += yb; }
    }
    if (lane == 31) { wredf[wid] = xf; wredb[wid] = xb; }
    __syncthreads();
    if (wid == 0) {
        float wf = wredf[lane], wb = wredb[lane];
#pragma unroll
        for (int d = 1; d < 32; d <<= 1) {
            float yf = __shfl_up_sync(0xFFFFFFFFu, wf, d);
            float yb = __shfl_up_sync(0xFFFFFFFFu, wb, d);
            if (lane >= d) { wf += yf; wb += yb; }
        }
        wredf[lane] = wf; wredb[lane] = wb;
    }
    __syncthreads();
    {
        float offf = (xf - tf) + (wid > 0 ? wredf[wid - 1] : 0.0f);
        float offb = (xb - tb) + (wid > 0 ? wredb[wid - 1] : 0.0f);
#pragma unroll
        for (int j = 0; j < CH; j++) {
            qf[pidx(CH * tid + j)] = offf + qfv[j];
            qb[pidx(CH * tid + j)] = offb + qbv[j];
        }
    }
    __syncthreads();

    const float invZ1 = 1.0f / Z1;
    float* outb = out + (size_t)blockIdx.x * F * L;

    // ---- Phase 5a: channel 0 (windows), 2 x STG.128 ----
#pragma unroll
    for (int g = 0; g < 2; g++) {
        float o[4];
#pragma unroll
        for (int e = 0; e < 4; e++) {
            int t = CH * tid + 4 * g + e;
            float b = bcd[4 * g + e];
            float wfv = ((t - 16 >= 0) ? qf[pidx(t - 16)] : 0.0f)
                      - ((t - 76 >= 0) ? qf[pidx(t - 76)] : 0.0f);
            int hi = t + 75; if (hi > L - 1) hi = L - 1;
            int lo = t + 15; if (lo > L - 1) lo = L - 1;
            float wbv = qb[pidx(hi)] - qb[pidx(lo)];
            float cf = b * k * wfv;
            float cb = b * k * wbv;
            float num = cf * b + b * cb + b * b;
            o[e] = clip01(num / adjv(b) * invZ1);
        }
        float4 v4 = make_float4(o[0], o[1], o[2], o[3]);
        *reinterpret_cast<float4*>(outb + CH * tid + 4 * g) = v4;
    }

    // ---- Phase 5b: channels 1..8, L2-hot reload, register transpose, STG.128 ----
#pragma unroll
    for (int h = 0; h < 2; h++) {
        // rows r0..r0+3, r0 = 8*tid + 4*h; 36 floats = 9 float4
        float w[36];
        const float4* gg = reinterpret_cast<const float4*>(gin) + tid * 18 + 9 * h;
#pragma unroll
        for (int v = 0; v < 9; v++) {
            float4 q = gg[v];
            w[4 * v + 0] = q.x; w[4 * v + 1] = q.y;
            w[4 * v + 2] = q.z; w[4 * v + 3] = q.w;
        }
#pragma unroll
        for (int ch = 1; ch < F; ch++) {
            float o[4];
#pragma unroll
            for (int r = 0; r < 4; r++) {
                float v = w[r * 9 + ch];
                o[r] = clip01(v * v / adjv(v) * invZ1);
            }
            float4 v4 = make_float4(o[0], o[1], o[2], o[3]);
            *reinterpret_cast<float4*>(outb + (size_t)ch * L + CH * tid + 4 * h) = v4;
        }
    }
}

extern "C" void kernel_launch(void* const* d_in, const int* in_sizes, int n_in,
                              void* d_out, int out_size) {
    const float* conc = (const float*)d_in[0];
    const float* kern = (const float*)d_in[1];
    float* out = (float*)d_out;
    const int B = in_sizes[0] / (L * F);

    const size_t smem = (size_t)3 * PL * sizeof(float);  // 110,592 B
    cudaFuncSetAttribute(kenneth_kernel,
                         cudaFuncAttributeMaxDynamicSharedMemorySize, (int)smem);
    kenneth_kernel<<<B, NT, smem>>>(conc, kern, out);
}

// round 5
// speedup vs baseline: 1.5146x; 1.5146x over previous
#include <cuda_runtime.h>

#define L    8192
#define F    9
#define NT   1024
#define CH   8                // rows per thread
#define PL   9216             // padded length: L + L/8
#define TILE 9216             // floats per tile = NT * F

__device__ __forceinline__ int pidx(int t) { return t + (t >> 3); }
__device__ __forceinline__ float clip01(float x) { return fminf(fmaxf(x, 0.0f), 0.9999f); }

__global__ __launch_bounds__(NT, 1)
void kenneth_kernel(const float* __restrict__ conc,
                    const float* __restrict__ kern,
                    float* __restrict__ out) {
    extern __shared__ float sm[];
    float* sb = sm;            // bcd (padded)
    float* sp = sm + PL;       // rowsum -> P (padded)
    float* qf = sm + 2 * PL;   // stage buf A / Q_f (padded)
    float* qb = sm + 3 * PL;   // stage buf B / Q_b (padded)
    __shared__ float wredp[32], wredf[32], wredb[32];

    const int tid  = threadIdx.x;
    const int lane = tid & 31;
    const int wid  = tid >> 5;
    const float k  = kern[0];
    const float* gin = conc + (size_t)blockIdx.x * (L * F);
    float* outb = out + (size_t)blockIdx.x * (F * L);

    float bcd[CH];
    float ld[9];

    // ---- Phase A: staged coalesced input pass; bcd -> sb, rowsum -> sp ----
#pragma unroll
    for (int v = 0; v < 9; v++) ld[v] = gin[v * NT + tid];
#pragma unroll
    for (int ii = 0; ii < CH; ii++) {
        float* stg = (ii & 1) ? qb : qf;
#pragma unroll
        for (int v = 0; v < 9; v++) stg[v * NT + tid] = ld[v];
        __syncthreads();
        if (ii < CH - 1) {
            const float* g = gin + (ii + 1) * TILE;
#pragma unroll
            for (int v = 0; v < 9; v++) ld[v] = g[v * NT + tid];
        }
        float s0 = stg[9 * tid];
        float acc = s0;
#pragma unroll
        for (int c = 1; c < 9; c++) acc += stg[9 * tid + c];
        bcd[ii] = s0;
        int t = ii * NT + tid;
        sb[pidx(t)] = s0;
        sp[pidx(t)] = acc;
    }
    __syncthreads();

    // ---- Phase B: P = 1 + inclusive cumsum(rowsum), chunked ownership ----
    const int base = CH * tid;
    {
        float pv[CH];
        float run = 0.0f;
#pragma unroll
        for (int j = 0; j < CH; j++) { run += sp[pidx(base + j)]; pv[j] = run; }
        float x = run;
#pragma unroll
        for (int d = 1; d < 32; d <<= 1) {
            float y = __shfl_up_sync(0xFFFFFFFFu, x, d);
            if (lane >= d) x += y;
        }
        if (lane == 31) wredp[wid] = x;
        __syncthreads();
        if (wid == 0) {
            float w = wredp[lane];
#pragma unroll
            for (int d = 1; d < 32; d <<= 1) {
                float y = __shfl_up_sync(0xFFFFFFFFu, w, d);
                if (lane >= d) w += y;
            }
            wredp[lane] = w;
        }
        __syncthreads();
        float off = 1.0f + (x - run) + (wid > 0 ? wredp[wid - 1] : 0.0f);
#pragma unroll
        for (int j = 0; j < CH; j++) sp[pidx(base + j)] = off + pv[j];
    }
    __syncthreads();

    const float Z1 = sp[pidx(L - 1)];
    const float C2 = Z1 + 1.0f;
    const float invZ1 = 1.0f / Z1;

    // ---- Phase C: build q_f/q_b and fused dual scan ----
    {
        float qfv[CH], qbv[CH];
#pragma unroll
        for (int j = 0; j < CH; j++) {
            int i = base + j;
            float b  = sb[pidx(i)];
            float pf = (i >= 14)    ? sp[pidx(i - 14)]        : 1.0f;
            float sv = (i + 14 < L) ? (C2 - sp[pidx(i + 13)]) : 1.0f;
            qfv[j] = b * pf;
            qbv[j] = b * sv;
        }
#pragma unroll
        for (int j = 1; j < CH; j++) { qfv[j] += qfv[j - 1]; qbv[j] += qbv[j - 1]; }
        float tf = qfv[CH - 1], tb = qbv[CH - 1];
        float xf = tf, xb = tb;
#pragma unroll
        for (int d = 1; d < 32; d <<= 1) {
            float yf = __shfl_up_sync(0xFFFFFFFFu, xf, d);
            float yb = __shfl_up_sync(0xFFFFFFFFu, xb, d);
            if (lane >= d) { xf += yf; xb += yb; }
        }
        if (lane == 31) { wredf[wid] = xf; wredb[wid] = xb; }
        __syncthreads();
        if (wid == 0) {
            float wf = wredf[lane], wb = wredb[lane];
#pragma unroll
            for (int d = 1; d < 32; d <<= 1) {
                float yf = __shfl_up_sync(0xFFFFFFFFu, wf, d);
                float yb = __shfl_up_sync(0xFFFFFFFFu, wb, d);
                if (lane >= d) { wf += yf; wb += yb; }
            }
            wredf[lane] = wf; wredb[lane] = wb;
        }
        __syncthreads();
        float offf = (xf - tf) + (wid > 0 ? wredf[wid - 1] : 0.0f);
        float offb = (xb - tb) + (wid > 0 ? wredb[wid - 1] : 0.0f);
#pragma unroll
        for (int j = 0; j < CH; j++) {
            qf[pidx(base + j)] = offf + qfv[j];
            qb[pidx(base + j)] = offb + qbv[j];
        }
    }
    __syncthreads();

    // ---- Phase D: channel 0 (windows), strided, coalesced, division-free ----
#pragma unroll
    for (int ii = 0; ii < CH; ii++) {
        int t = ii * NT + tid;
        float b = bcd[ii];
        float wfv = ((t >= 16) ? qf[pidx(t - 16)] : 0.0f)
                  - ((t >= 76) ? qf[pidx(t - 76)] : 0.0f);
        int hi = t + 75; if (hi > L - 1) hi = L - 1;
        int lo = t + 15; if (lo > L - 1) lo = L - 1;
        float wbv = qb[pidx(hi)] - qb[pidx(lo)];
        float t0 = fmaf(k, wfv + wbv, 1.0f);       // num = b^2 * t0
        float o = b * t0 * invZ1;                   // b > eps: num/adj(b) = b*t0
        if (!(b > 1e-13f)) o = (b * b * t0) / (b + 1.0f) * invZ1;
        outb[t] = clip01(o);
    }

    // ---- Phase E: channels 1..8, staged coalesced reload (L2-hot), division-free ----
#pragma unroll
    for (int v = 0; v < 9; v++) ld[v] = gin[v * NT + tid];
#pragma unroll
    for (int ii = 0; ii < CH; ii++) {
        float* stg = (ii & 1) ? sp : sb;
#pragma unroll
        for (int v = 0; v < 9; v++) stg[v * NT + tid] = ld[v];
        __syncthreads();
        if (ii < CH - 1) {
            const float* g = gin + (ii + 1) * TILE;
#pragma unroll
            for (int v = 0; v < 9; v++) ld[v] = g[v * NT + tid];
        }
        int t = ii * NT + tid;
#pragma unroll
        for (int ch = 1; ch < 9; ch++) {
            float v = stg[9 * tid + ch];
            float u = v * invZ1;                    // v > eps: v^2/adj(v) = v
            if (!(v > 1e-13f)) u = (v * v) / (v + 1.0f) * invZ1;
            outb[(size_t)ch * L + t] = clip01(u);
        }
    }
}

extern "C" void kernel_launch(void* const* d_in, const int* in_sizes, int n_in,
                              void* d_out, int out_size) {
    const float* conc = (const float*)d_in[0];
    const float* kern = (const float*)d_in[1];
    float* out = (float*)d_out;
    const int B = in_sizes[0] / (L * F);

    const size_t smem = (size_t)4 * PL * sizeof(float);  // 147,456 B
    cudaFuncSetAttribute(kenneth_kernel,
                         cudaFuncAttributeMaxDynamicSharedMemorySize, (int)smem);
    kenneth_kernel<<<B, NT, smem>>>(conc, kern, out);
}

// round 6
// speedup vs baseline: 1.7595x; 1.1617x over previous
#include <cuda_runtime.h>

#define L    8192
#define F    9
#define NT   1024
#define CH   8                // rows/tiles per thread
#define PL   9216             // padded length: L + L/8
#define TILE 9216             // floats per tile = NT * F

__device__ __forceinline__ int pidx(int t) { return t + (t >> 3); }
__device__ __forceinline__ float clip01(float x) { return fminf(fmaxf(x, 0.0f), 0.9999f); }

__global__ __launch_bounds__(NT, 1)
void kenneth_kernel(const float* __restrict__ conc,
                    const float* __restrict__ kern,
                    float* __restrict__ out) {
    extern __shared__ float sm[];
    float* sb = sm;            // bcd (padded)
    float* sp = sm + PL;       // rowsum -> P (padded)
    float* qf = sm + 2 * PL;   // stage buf A / Q_f (padded)
    float* qb = sm + 3 * PL;   // stage buf B / Q_b (padded)
    __shared__ float wredp[32], wredf[32], wredb[32];

    const int tid  = threadIdx.x;
    const int lane = tid & 31;
    const int wid  = tid >> 5;
    const float k  = kern[0];
    const float* gin = conc + (size_t)blockIdx.x * (L * F);
    float* outb = out + (size_t)blockIdx.x * (F * L);

    float bcd[CH];
    float ld[9];

    // ---- Phase A: single staged input pass.
    //      bcd -> sb, rowsum -> sp, RAW ch1..8 values -> outb (rescaled later).
#pragma unroll
    for (int v = 0; v < 9; v++) ld[v] = gin[v * NT + tid];
#pragma unroll
    for (int ii = 0; ii < CH; ii++) {
        float* stg = (ii & 1) ? qb : qf;
#pragma unroll
        for (int v = 0; v < 9; v++) stg[v * NT + tid] = ld[v];
        __syncthreads();
        if (ii < CH - 1) {
            const float* g = gin + (ii + 1) * TILE;
#pragma unroll
            for (int v = 0; v < 9; v++) ld[v] = g[v * NT + tid];
        }
        int t = ii * NT + tid;
        float r0 = stg[9 * tid];
        float acc = r0;
#pragma unroll
        for (int c = 1; c < 9; c++) {
            float v = stg[9 * tid + c];
            acc += v;
            outb[(size_t)c * L + t] = v;      // raw value, coalesced
        }
        bcd[ii] = r0;
        sb[pidx(t)] = r0;
        sp[pidx(t)] = acc;
    }
    __syncthreads();

    // ---- Phase B: P = 1 + inclusive cumsum(rowsum), chunked ownership ----
    const int base = CH * tid;
    {
        float pv[CH];
        float run = 0.0f;
#pragma unroll
        for (int j = 0; j < CH; j++) { run += sp[pidx(base + j)]; pv[j] = run; }
        float x = run;
#pragma unroll
        for (int d = 1; d < 32; d <<= 1) {
            float y = __shfl_up_sync(0xFFFFFFFFu, x, d);
            if (lane >= d) x += y;
        }
        if (lane == 31) wredp[wid] = x;
        __syncthreads();
        if (wid == 0) {
            float w = wredp[lane];
#pragma unroll
            for (int d = 1; d < 32; d <<= 1) {
                float y = __shfl_up_sync(0xFFFFFFFFu, w, d);
                if (lane >= d) w += y;
            }
            wredp[lane] = w;
        }
        __syncthreads();
        float off = 1.0f + (x - run) + (wid > 0 ? wredp[wid - 1] : 0.0f);
#pragma unroll
        for (int j = 0; j < CH; j++) sp[pidx(base + j)] = off + pv[j];
    }
    __syncthreads();

    const float Z1 = sp[pidx(L - 1)];
    const float C2 = Z1 + 1.0f;
    const float invZ1 = 1.0f / Z1;

    // ---- Phase C: build q_f/q_b and fused dual scan ----
    {
        float qfv[CH], qbv[CH];
#pragma unroll
        for (int j = 0; j < CH; j++) {
            int i = base + j;
            float b  = sb[pidx(i)];
            float pf = (i >= 14)    ? sp[pidx(i - 14)]        : 1.0f;
            float sv = (i + 14 < L) ? (C2 - sp[pidx(i + 13)]) : 1.0f;
            qfv[j] = b * pf;
            qbv[j] = b * sv;
        }
#pragma unroll
        for (int j = 1; j < CH; j++) { qfv[j] += qfv[j - 1]; qbv[j] += qbv[j - 1]; }
        float tf = qfv[CH - 1], tb = qbv[CH - 1];
        float xf = tf, xb = tb;
#pragma unroll
        for (int d = 1; d < 32; d <<= 1) {
            float yf = __shfl_up_sync(0xFFFFFFFFu, xf, d);
            float yb = __shfl_up_sync(0xFFFFFFFFu, xb, d);
            if (lane >= d) { xf += yf; xb += yb; }
        }
        if (lane == 31) { wredf[wid] = xf; wredb[wid] = xb; }
        __syncthreads();
        if (wid == 0) {
            float wf = wredf[lane], wb = wredb[lane];
#pragma unroll
            for (int d = 1; d < 32; d <<= 1) {
                float yf = __shfl_up_sync(0xFFFFFFFFu, wf, d);
                float yb = __shfl_up_sync(0xFFFFFFFFu, wb, d);
                if (lane >= d) { wf += yf; wb += yb; }
            }
            wredf[lane] = wf; wredb[lane] = wb;
        }
        __syncthreads();
        float offf = (xf - tf) + (wid > 0 ? wredf[wid - 1] : 0.0f);
        float offb = (xb - tb) + (wid > 0 ? wredb[wid - 1] : 0.0f);
#pragma unroll
        for (int j = 0; j < CH; j++) {
            qf[pidx(base + j)] = offf + qfv[j];
            qb[pidx(base + j)] = offb + qbv[j];
        }
    }
    __syncthreads();

    // ---- Phase D: channel 0 (windows), strided, coalesced, division-free ----
#pragma unroll
    for (int ii = 0; ii < CH; ii++) {
        int t = ii * NT + tid;
        float b = bcd[ii];
        float wfv = ((t >= 16) ? qf[pidx(t - 16)] : 0.0f)
                  - ((t >= 76) ? qf[pidx(t - 76)] : 0.0f);
        int hi = t + 75; if (hi > L - 1) hi = L - 1;
        int lo = t + 15; if (lo > L - 1) lo = L - 1;
        float wbv = qb[pidx(hi)] - qb[pidx(lo)];
        float t0 = fmaf(k, wfv + wbv, 1.0f);        // num = b^2 * t0
        float o = b * t0 * invZ1;                    // b > eps: num/adj(b) = b*t0
        if (!(b > 1e-13f)) o = (b * b * t0) / (b + 1.0f) * invZ1;
        outb[t] = clip01(o);
    }

    // ---- Phase E: rescale raw ch1..8 in-place, float4, L2-hot ----
    {
        float4* o4 = reinterpret_cast<float4*>(outb + L);   // 8*L floats = 16384 float4
#pragma unroll
        for (int g = 0; g < 16; g++) {
            float4 q = o4[g * NT + tid];
            float* e = &q.x;
#pragma unroll
            for (int c = 0; c < 4; c++) {
                float v = e[c];
                float w = (v > 1e-13f) ? v : (v * v) / (v + 1.0f);
                e[c] = clip01(w * invZ1);
            }
            o4[g * NT + tid] = q;
        }
    }
}

extern "C" void kernel_launch(void* const* d_in, const int* in_sizes, int n_in,
                              void* d_out, int out_size) {
    const float* conc = (const float*)d_in[0];
    const float* kern = (const float*)d_in[1];
    float* out = (float*)d_out;
    const int B = in_sizes[0] / (L * F);

    const size_t smem = (size_t)4 * PL * sizeof(float);  // 147,456 B
    cudaFuncSetAttribute(kenneth_kernel,
                         cudaFuncAttributeMaxDynamicSharedMemorySize, (int)smem);
    kenneth_kernel<<<B, NT, smem>>>(conc, kern, out);
}

// round 7
// speedup vs baseline: 2.4160x; 1.3731x over previous
#include <cuda_runtime.h>

#define L    8192
#define F    9
#define NT   1024
#define CH   8                // rows per thread
#define PL   9216             // padded length: L + L/8

__device__ __forceinline__ int pidx(int t) { return t + (t >> 3); }
__device__ __forceinline__ float clip01(float x) { return fminf(fmaxf(x, 0.0f), 0.9999f); }
__device__ __forceinline__ float sel4(int rw, float a, float b, float c, float d) {
    float r = a;
    if (rw == 1) r = b;
    if (rw == 2) r = c;
    if (rw == 3) r = d;
    return r;
}

__global__ __launch_bounds__(NT, 1)
void kenneth_kernel(const float* __restrict__ conc,
                    const float* __restrict__ kern,
                    float* __restrict__ out) {
    extern __shared__ float sm[];
    float* sb = sm;            // bcd (padded)
    float* sp = sm + PL;       // rowsum -> P (padded)
    float* qf = sm + 2 * PL;   // Q_f (padded)
    float* qb = sm + 3 * PL;   // Q_b (padded)
    __shared__ float wredp[32], wredf[32], wredb[32];
    __shared__ float sZ1;

    const int tid  = threadIdx.x;
    const int lane = tid & 31;
    const int wid  = tid >> 5;
    const float k  = kern[0];
    const float* gin = conc + (size_t)blockIdx.x * (L * F);
    float* outb = out + (size_t)blockIdx.x * (F * L);

    // ---- Phase Z: Z1 = 1 + sum(all inputs), flat coalesced float4 reduction ----
    {
        const float4* g4 = reinterpret_cast<const float4*>(gin);
        float tot = 0.0f;
#pragma unroll
        for (int g = 0; g < 18; g++) {
            float4 q = g4[g * NT + tid];
            tot += (q.x + q.y) + (q.z + q.w);
        }
#pragma unroll
        for (int d = 16; d >= 1; d >>= 1) tot += __shfl_xor_sync(0xFFFFFFFFu, tot, d);
        if (lane == 0) wredp[wid] = tot;
        __syncthreads();
        if (tid == 0) {
            float s = 0.0f;
#pragma unroll
            for (int i = 0; i < 32; i++) s += wredp[i];
            sZ1 = 1.0f + s;
        }
        __syncthreads();
    }
    const float Z1 = sZ1;
    const float C2 = Z1 + 1.0f;
    const float invZ1 = 1.0f / Z1;

    // ---- Phase A: direct row loads (3 aligned LDG.128/row), final ch1..8 stores ----
    float bcd[CH];
    const int rw = tid & 3;                 // 9t mod 4 == t mod 4, tile-invariant
#pragma unroll
    for (int ii = 0; ii < CH; ii++) {
        int t = ii * NT + tid;
        const float4* p4 = reinterpret_cast<const float4*>(gin) + ((9 * t) >> 2);
        float4 q0 = p4[0], q1 = p4[1], q2 = p4[2];
        float w[12] = { q0.x, q0.y, q0.z, q0.w,
                        q1.x, q1.y, q1.z, q1.w,
                        q2.x, q2.y, q2.z, q2.w };
        // row values v[c] = w[rw + c], c = 0..8
        float v[9];
#pragma unroll
        for (int c = 0; c < 9; c++) v[c] = sel4(rw, w[c], w[c + 1], w[c + 2], w[c + 3]);

        float b = v[0];
        float acc = v[0];
#pragma unroll
        for (int c = 1; c < 9; c++) acc += v[c];
        bcd[ii] = b;
        sb[pidx(t)] = b;
        sp[pidx(t)] = acc;

#pragma unroll
        for (int c = 1; c < 9; c++) {
            float vv = v[c];
            float u = (vv > 1e-13f) ? vv : (vv * vv) / (vv + 1.0f);
            outb[(size_t)c * L + t] = clip01(u * invZ1);
        }
    }
    __syncthreads();

    // ---- Phase B: P = 1 + inclusive cumsum(rowsum), chunked ownership ----
    const int base = CH * tid;
    {
        float pv[CH];
        float run = 0.0f;
#pragma unroll
        for (int j = 0; j < CH; j++) { run += sp[pidx(base + j)]; pv[j] = run; }
        float x = run;
#pragma unroll
        for (int d = 1; d < 32; d <<= 1) {
            float y = __shfl_up_sync(0xFFFFFFFFu, x, d);
            if (lane >= d) x += y;
        }
        if (lane == 31) wredp[wid] = x;
        __syncthreads();
        if (wid == 0) {
            float w = wredp[lane];
#pragma unroll
            for (int d = 1; d < 32; d <<= 1) {
                float y = __shfl_up_sync(0xFFFFFFFFu, w, d);
                if (lane >= d) w += y;
            }
            wredp[lane] = w;
        }
        __syncthreads();
        float off = 1.0f + (x - run) + (wid > 0 ? wredp[wid - 1] : 0.0f);
#pragma unroll
        for (int j = 0; j < CH; j++) sp[pidx(base + j)] = off + pv[j];
    }
    __syncthreads();

    // ---- Phase C: build q_f/q_b and fused dual scan ----
    {
        float qfv[CH], qbv[CH];
#pragma unroll
        for (int j = 0; j < CH; j++) {
            int i = base + j;
            float b  = sb[pidx(i)];
            float pf = (i >= 14)    ? sp[pidx(i - 14)]        : 1.0f;
            float sv = (i + 14 < L) ? (C2 - sp[pidx(i + 13)]) : 1.0f;
            qfv[j] = b * pf;
            qbv[j] = b * sv;
        }
#pragma unroll
        for (int j = 1; j < CH; j++) { qfv[j] += qfv[j - 1]; qbv[j] += qbv[j - 1]; }
        float tf = qfv[CH - 1], tb = qbv[CH - 1];
        float xf = tf, xb = tb;
#pragma unroll
        for (int d = 1; d < 32; d <<= 1) {
            float yf = __shfl_up_sync(0xFFFFFFFFu, xf, d);
            float yb = __shfl_up_sync(0xFFFFFFFFu, xb, d);
            if (lane >= d) { xf += yf; xb += yb; }
        }
        if (lane == 31) { wredf[wid] = xf; wredb[wid] = xb; }
        __syncthreads();
        if (wid == 0) {
            float wf = wredf[lane], wb = wredb[lane];
#pragma unroll
            for (int d = 1; d < 32; d <<= 1) {
                float yf = __shfl_up_sync(0xFFFFFFFFu, wf, d);
                float yb = __shfl_up_sync(0xFFFFFFFFu, wb, d);
                if (lane >= d) { wf += yf; wb += yb; }
            }
            wredf[lane] = wf; wredb[lane] = wb;
        }
        __syncthreads();
        float offf = (xf - tf) + (wid > 0 ? wredf[wid - 1] : 0.0f);
        float offb = (xb - tb) + (wid > 0 ? wredb[wid - 1] : 0.0f);
#pragma unroll
        for (int j = 0; j < CH; j++) {
            qf[pidx(base + j)] = offf + qfv[j];
            qb[pidx(base + j)] = offb + qbv[j];
        }
    }
    __syncthreads();

    // ---- Phase D: channel 0 (windows), strided, coalesced, division-free ----
#pragma unroll
    for (int ii = 0; ii < CH; ii++) {
        int t = ii * NT + tid;
        float b = bcd[ii];
        float wfv = ((t >= 16) ? qf[pidx(t - 16)] : 0.0f)
                  - ((t >= 76) ? qf[pidx(t - 76)] : 0.0f);
        int hi = t + 75; if (hi > L - 1) hi = L - 1;
        int lo = t + 15; if (lo > L - 1) lo = L - 1;
        float wbv = qb[pidx(hi)] - qb[pidx(lo)];
        float t0 = fmaf(k, wfv + wbv, 1.0f);        // num = b^2 * t0
        float o = b * t0 * invZ1;                    // b > eps: num/adj(b) = b*t0
        if (!(b > 1e-13f)) o = (b * b * t0) / (b + 1.0f) * invZ1;
        outb[t] = clip01(o);
    }
}

extern "C" void kernel_launch(void* const* d_in, const int* in_sizes, int n_in,
                              void* d_out, int out_size) {
    const float* conc = (const float*)d_in[0];
    const float* kern = (const float*)d_in[1];
    float* out = (float*)d_out;
    const int B = in_sizes[0] / (L * F);

    const size_t smem = (size_t)4 * PL * sizeof(float);  // 147,456 B
    cudaFuncSetAttribute(kenneth_kernel,
                         cudaFuncAttributeMaxDynamicSharedMemorySize, (int)smem);
    kenneth_kernel<<<B, NT, smem>>>(conc, kern, out);
}

// round 8
// speedup vs baseline: 2.4206x; 1.0019x over previous
#include <cuda_runtime.h>
#include <cstdint>

#define L      8192
#define F      9
#define NT     1024
#define CH     8                 // tiles (rows per thread)
#define PL     9216              // padded scan length: L + L/8
#define TFLOAT 9216              // floats per tile = NT * F
#define TBYTES 36864             // bytes per tile

__device__ __forceinline__ int pidx(int t) { return t + (t >> 3); }
__device__ __forceinline__ float clip01(float x) { return fminf(fmaxf(x, 0.0f), 0.9999f); }

__device__ __forceinline__ uint32_t smem_u32(const void* p) {
    uint32_t a;
    asm("{ .reg .u64 t; cvta.to.shared.u64 t, %1; cvt.u32.u64 %0, t; }" : "=r"(a) : "l"(p));
    return a;
}
__device__ __forceinline__ void mbar_init(uint32_t mbar, uint32_t cnt) {
    asm volatile("mbarrier.init.shared.b64 [%0], %1;" :: "r"(mbar), "r"(cnt) : "memory");
}
__device__ __forceinline__ void mbar_expect_tx(uint32_t mbar, uint32_t bytes) {
    asm volatile("mbarrier.arrive.expect_tx.shared.b64 _, [%0], %1;" :: "r"(mbar), "r"(bytes) : "memory");
}
__device__ __forceinline__ void bulk_g2s(uint32_t dst, const void* src, uint32_t bytes, uint32_t mbar) {
    asm volatile("cp.async.bulk.shared::cta.global.mbarrier::complete_tx::bytes [%0], [%1], %2, [%3];"
                 :: "r"(dst), "l"(src), "r"(bytes), "r"(mbar) : "memory");
}
__device__ __forceinline__ void mbar_wait(uint32_t mbar, uint32_t parity) {
    asm volatile(
        "{\n\t"
        ".reg .pred P;\n\t"
        "WAIT_%=:\n\t"
        "mbarrier.try_wait.parity.acquire.cta.shared::cta.b64 P, [%0], %1, 0x989680;\n\t"
        "@P bra.uni DONE_%=;\n\t"
        "bra.uni WAIT_%=;\n\t"
        "DONE_%=:\n\t"
        "}"
        :: "r"(mbar), "r"(parity) : "memory");
}

__global__ __launch_bounds__(NT, 1)
void kenneth_kernel(const float* __restrict__ conc,
                    const float* __restrict__ kern,
                    float* __restrict__ out) {
    extern __shared__ float sm[];
    float* sb = sm;            // bcd (padded)
    float* sp = sm + PL;       // rowsum -> P (padded)
    float* qf = sm + 2 * PL;   // stage buf 0 / Q_f
    float* qb = sm + 3 * PL;   // stage buf 1 / Q_b
    __shared__ float wredp[32], wredf[32], wredb[32];
    __shared__ float sZ1;
    __shared__ uint64_t mbar_s[2];

    const int tid  = threadIdx.x;
    const int lane = tid & 31;
    const int wid  = tid >> 5;
    const float k  = kern[0];
    const float* gin = conc + (size_t)blockIdx.x * (L * F);
    float* outb = out + (size_t)blockIdx.x * (F * L);

    const uint32_t mb0 = smem_u32(&mbar_s[0]);
    const uint32_t mb1 = smem_u32(&mbar_s[1]);
    const uint32_t stg0 = smem_u32(qf);
    const uint32_t stg1 = smem_u32(qb);

    // ---- Init mbarriers + kick off first two tile DMAs ----
    if (tid == 0) {
        mbar_init(mb0, 1);
        mbar_init(mb1, 1);
    }
    __syncthreads();
    if (tid == 0) {
        mbar_expect_tx(mb0, TBYTES);
        bulk_g2s(stg0, gin, TBYTES, mb0);
        mbar_expect_tx(mb1, TBYTES);
        bulk_g2s(stg1, gin + TFLOAT, TBYTES, mb1);
    }

    // ---- Phase Z: Z1 = 1 + sum(all inputs), coalesced float4 reduction ----
    // (overlaps with the in-flight bulk copies)
    {
        const float4* g4 = reinterpret_cast<const float4*>(gin);
        float tot = 0.0f;
#pragma unroll
        for (int g = 0; g < 18; g++) {
            float4 q = g4[g * NT + tid];
            tot += (q.x + q.y) + (q.z + q.w);
        }
#pragma unroll
        for (int d = 16; d >= 1; d >>= 1) tot += __shfl_xor_sync(0xFFFFFFFFu, tot, d);
        if (lane == 0) wredp[wid] = tot;
        __syncthreads();
        if (tid == 0) {
            float s = 0.0f;
#pragma unroll
            for (int i = 0; i < 32; i++) s += wredp[i];
            sZ1 = 1.0f + s;
        }
        __syncthreads();
    }
    const float Z1 = sZ1;
    const float C2 = Z1 + 1.0f;
    const float invZ1 = 1.0f / Z1;

    // ---- Phase A: staged tiles; bcd -> sb, rowsum -> sp, final ch1..8 stores ----
    float bcd[CH];
#pragma unroll
    for (int ii = 0; ii < CH; ii++) {
        float* stg = (ii & 1) ? qb : qf;
        mbar_wait((ii & 1) ? mb1 : mb0, (ii >> 1) & 1);

        float v[9];
#pragma unroll
        for (int c = 0; c < 9; c++) v[c] = stg[9 * tid + c];

        __syncthreads();  // all threads done with this buffer
        if (tid == 0 && ii + 2 < CH) {
            uint32_t mb = (ii & 1) ? mb1 : mb0;
            mbar_expect_tx(mb, TBYTES);
            bulk_g2s((ii & 1) ? stg1 : stg0, gin + (ii + 2) * TFLOAT, TBYTES, mb);
        }

        int t = ii * NT + tid;
        float b = v[0];
        float acc = v[0];
#pragma unroll
        for (int c = 1; c < 9; c++) acc += v[c];
        bcd[ii] = b;
        sb[pidx(t)] = b;
        sp[pidx(t)] = acc;

#pragma unroll
        for (int c = 1; c < 9; c++) {
            float vv = v[c];
            float u = (vv > 1e-13f) ? vv : (vv * vv) / (vv + 1.0f);
            outb[(size_t)c * L + t] = clip01(u * invZ1);
        }
    }
    __syncthreads();

    // ---- Phase B: P = 1 + inclusive cumsum(rowsum), chunked ownership ----
    const int base = CH * tid;
    {
        float pv[CH];
        float run = 0.0f;
#pragma unroll
        for (int j = 0; j < CH; j++) { run += sp[pidx(base + j)]; pv[j] = run; }
        float x = run;
#pragma unroll
        for (int d = 1; d < 32; d <<= 1) {
            float y = __shfl_up_sync(0xFFFFFFFFu, x, d);
            if (lane >= d) x += y;
        }
        if (lane == 31) wredp[wid] = x;
        __syncthreads();
        if (wid == 0) {
            float w = wredp[lane];
#pragma unroll
            for (int d = 1; d < 32; d <<= 1) {
                float y = __shfl_up_sync(0xFFFFFFFFu, w, d);
                if (lane >= d) w += y;
            }
            wredp[lane] = w;
        }
        __syncthreads();
        float off = 1.0f + (x - run) + (wid > 0 ? wredp[wid - 1] : 0.0f);
#pragma unroll
        for (int j = 0; j < CH; j++) sp[pidx(base + j)] = off + pv[j];
    }
    __syncthreads();

    // ---- Phase C: build q_f/q_b and fused dual scan ----
    {
        float qfv[CH], qbv[CH];
#pragma unroll
        for (int j = 0; j < CH; j++) {
            int i = base + j;
            float b  = sb[pidx(i)];
            float pf = (i >= 14)    ? sp[pidx(i - 14)]        : 1.0f;
            float sv = (i + 14 < L) ? (C2 - sp[pidx(i + 13)]) : 1.0f;
            qfv[j] = b * pf;
            qbv[j] = b * sv;
        }
#pragma unroll
        for (int j = 1; j < CH; j++) { qfv[j] += qfv[j - 1]; qbv[j] += qbv[j - 1]; }
        float tf = qfv[CH - 1], tb = qbv[CH - 1];
        float xf = tf, xb = tb;
#pragma unroll
        for (int d = 1; d < 32; d <<= 1) {
            float yf = __shfl_up_sync(0xFFFFFFFFu, xf, d);
            float yb = __shfl_up_sync(0xFFFFFFFFu, xb, d);
            if (lane >= d) { xf += yf; xb += yb; }
        }
        if (lane == 31) { wredf[wid] = xf; wredb[wid] = xb; }
        __syncthreads();
        if (wid == 0) {
            float wf = wredf[lane], wb = wredb[lane];
#pragma unroll
            for (int d = 1; d < 32; d <<= 1) {
                float yf = __shfl_up_sync(0xFFFFFFFFu, wf, d);
                float yb = __shfl_up_sync(0xFFFFFFFFu, wb, d);
                if (lane >= d) { wf += yf; wb += yb; }
            }
            wredf[lane] = wf; wredb[lane] = wb;
        }
        __syncthreads();
        float offf = (xf - tf) + (wid > 0 ? wredf[wid - 1] : 0.0f);
        float offb = (xb - tb) + (wid > 0 ? wredb[wid - 1] : 0.0f);
#pragma unroll
        for (int j = 0; j < CH; j++) {
            qf[pidx(base + j)] = offf + qfv[j];
            qb[pidx(base + j)] = offb + qbv[j];
        }
    }
    __syncthreads();

    // ---- Phase D: channel 0 (windows), strided, coalesced, division-free ----
#pragma unroll
    for (int ii = 0; ii < CH; ii++) {
        int t = ii * NT + tid;
        float b = bcd[ii];
        float wfv = ((t >= 16) ? qf[pidx(t - 16)] : 0.0f)
                  - ((t >= 76) ? qf[pidx(t - 76)] : 0.0f);
        int hi = t + 75; if (hi > L - 1) hi = L - 1;
        int lo = t + 15; if (lo > L - 1) lo = L - 1;
        float wbv = qb[pidx(hi)] - qb[pidx(lo)];
        float t0 = fmaf(k, wfv + wbv, 1.0f);        // num = b^2 * t0
        float o = b * t0 * invZ1;                    // b > eps: num/adj(b) = b*t0
        if (!(b > 1e-13f)) o = (b * b * t0) / (b + 1.0f) * invZ1;
        outb[t] = clip01(o);
    }
}

extern "C" void kernel_launch(void* const* d_in, const int* in_sizes, int n_in,
                              void* d_out, int out_size) {
    const float* conc = (const float*)d_in[0];
    const float* kern = (const float*)d_in[1];
    float* out = (float*)d_out;
    const int B = in_sizes[0] / (L * F);

    const size_t smem = (size_t)4 * PL * sizeof(float);  // 147,456 B dynamic
    cudaFuncSetAttribute(kenneth_kernel,
                         cudaFuncAttributeMaxDynamicSharedMemorySize, (int)smem);
    kenneth_kernel<<<B, NT, smem>>>(conc, kern, out);
}